// round 11
// baseline (speedup 1.0000x reference)
#include <cuda_runtime.h>
#include <stdint.h>

#define B_  32
#define H_  512
#define W_  512
#define PIX_PER_IMG (H_ * W_)                    // 262144
#define CHUNKS 64                                // moments blocks per batch
#define F4_PER_CHUNK (PIX_PER_IMG / CHUNKS / 4)  // 1024 float4 per block
#define F4_PER_THREAD (F4_PER_CHUNK / 256)       // 4 (front-batched, MLP_p1=4)
#define SHIFT_ELEMS 8
#define SGRID (B_ * (PIX_PER_IMG / (256 * SHIFT_ELEMS)))  // 4096 shift blocks
#define FP_SCALE 1048576.0f                      // 2^20 (exact float scaling)

// Scratch (no allocations allowed) — zero-init; self-reset by shift kernel.
__device__ long long    g_tot[B_ * 3];   // fixed-point (m00,m10,m01) per batch
__device__ unsigned int g_done;          // shift completion counter

// ---------------------------------------------------------------------------
// Stage 1: mk moments. Block partials reduced deterministically (butterfly +
// fixed-order smem sum), then committed as 2^20 fixed-point via integer
// atomicAdd — associative, so the total is deterministic regardless of
// arrival order. No inter-block protocol, no finalize stage.
// ---------------------------------------------------------------------------
__global__ __launch_bounds__(256) void moments_kernel(const float* __restrict__ mk)
{
    const int b     = blockIdx.y;
    const int chunk = blockIdx.x;       // 0..63
    const int t     = threadIdx.x;      // 0..255
    const int lane  = t & 31;
    const int wid   = t >> 5;           // 0..7

    const float4* base =
        (const float4*)(mk + (size_t)b * PIX_PER_IMG) + chunk * F4_PER_CHUNK;

    // Front-batch all 4 independent loads (MLP_p1=4).
    float4 v[F4_PER_THREAD];
#pragma unroll
    for (int i = 0; i < F4_PER_THREAD; i++)
        v[i] = base[t + i * 256];

    float s0 = 0.f, s1 = 0.f, s2 = 0.f;
#pragma unroll
    for (int i = 0; i < F4_PER_THREAD; i++) {
        const int p = chunk * (F4_PER_CHUNK * 4) + (t + i * 256) * 4;
        const int h = p >> 9;
        const int w = p & (W_ - 1);
        const float ry  = (float)(h - (H_ / 2));
        const float rx0 = (float)(w - (W_ / 2));
        const float sum = v[i].x + v[i].y + v[i].z + v[i].w;
        s0 += sum;
        s2 += ry * sum;
        s1 += rx0 * v[i].x + (rx0 + 1.f) * v[i].y + (rx0 + 2.f) * v[i].z
            + (rx0 + 3.f) * v[i].w;
    }

    // Warp butterfly reduce (deterministic fixed order)
#pragma unroll
    for (int m = 16; m > 0; m >>= 1) {
        s0 += __shfl_xor_sync(0xffffffffu, s0, m);
        s1 += __shfl_xor_sync(0xffffffffu, s1, m);
        s2 += __shfl_xor_sync(0xffffffffu, s2, m);
    }

    __shared__ float w0[8], w1[8], w2[8];
    if (lane == 0) { w0[wid] = s0; w1[wid] = s1; w2[wid] = s2; }
    __syncthreads();

    if (t == 0) {
        float r0 = 0.f, r1 = 0.f, r2 = 0.f;
#pragma unroll
        for (int i = 0; i < 8; i++) { r0 += w0[i]; r1 += w1[i]; r2 += w2[i]; }
        // Exact *2^20 scaling; llrintf error <= 0.5 fixed units per block.
        atomicAdd((unsigned long long*)&g_tot[b * 3 + 0],
                  (unsigned long long)llrintf(r0 * FP_SCALE));
        atomicAdd((unsigned long long*)&g_tot[b * 3 + 1],
                  (unsigned long long)llrintf(r1 * FP_SCALE));
        atomicAdd((unsigned long long*)&g_tot[b * 3 + 2],
                  (unsigned long long)llrintf(r2 * FP_SCALE));
    }
}

// ---------------------------------------------------------------------------
// Stage 2: shifted copy. Each block derives (dx,dy) from the fixed-point
// totals itself (kernel boundary guarantees visibility of the atomics).
// m10/m00 = tot1 / max(0.001*2^20, tot0); dx = rint(...) — round-half-even,
// matching jnp.round. Last block resets totals for the next graph replay.
// ---------------------------------------------------------------------------
__global__ __launch_bounds__(256) void shift_kernel(const float4* __restrict__ x,
                                                    float4* __restrict__ out)
{
    const int b    = blockIdx.y;
    const int base = blockIdx.x * (256 * SHIFT_ELEMS);   // pixel base in image
    const int t    = threadIdx.x;

    const long long t0 = g_tot[b * 3 + 0];
    const long long t1 = g_tot[b * 3 + 1];
    const long long t2 = g_tot[b * 3 + 2];
    const double den = fmax(1048.576, (double)t0);       // 0.001 * 2^20 floor
    const int dx = (int)rint((double)t1 / den);
    const int dy = (int)rint((double)t2 / den);

    const float4* xb = x + ((size_t)b << 18);
    float4* ob       = out + ((size_t)b << 18);

    float4 v[SHIFT_ELEMS];
#pragma unroll
    for (int k = 0; k < SHIFT_ELEMS; k++) {
        const int p = base + k * 256 + t;
        const int h = p >> 9;
        const int w = p & (W_ - 1);
        const int sh = h + dy;
        const int sw = w + dx;
        v[k] = make_float4(0.f, 0.f, 0.f, 0.f);
        if ((unsigned)sh < (unsigned)H_ && (unsigned)sw < (unsigned)W_)
            v[k] = xb[(sh << 9) + sw];
    }
#pragma unroll
    for (int k = 0; k < SHIFT_ELEMS; k++)
        ob[base + k * 256 + t] = v[k];

    // Replay cleanup: every block has read g_tot before incrementing g_done
    // (program order + syncthreads), so the last block may safely reset.
    __syncthreads();
    if (t == 0) {
        if (atomicAdd(&g_done, 1u) == SGRID - 1) {
#pragma unroll
            for (int i = 0; i < B_ * 3; i++) g_tot[i] = 0ll;
            g_done = 0u;
            __threadfence();
        }
    }
}

// ---------------------------------------------------------------------------
extern "C" void kernel_launch(void* const* d_in, const int* in_sizes, int n_in,
                              void* d_out, int out_size)
{
    const float* x  = (const float*)d_in[0];   // [32,512,512,4]
    const float* mk = (const float*)d_in[1];   // [32,512,512,1]

    dim3 g1(CHUNKS, B_);                       // (64, 32) = 2048 blocks
    moments_kernel<<<g1, 256>>>(mk);

    dim3 g2(PIX_PER_IMG / (256 * SHIFT_ELEMS), B_);   // (128, 32)
    shift_kernel<<<g2, 256>>>((const float4*)x, (float4*)d_out);
}

// round 12
// speedup vs baseline: 1.1064x; 1.1064x over previous
#include <cuda_runtime.h>
#include <stdint.h>

#define B_  32
#define H_  512
#define W_  512
#define PIX_PER_IMG (H_ * W_)                    // 262144
#define CHUNKS 64                                // moments blocks per batch
#define F4_PER_CHUNK (PIX_PER_IMG / CHUNKS / 4)  // 1024 float4 per block
#define F4_PER_THREAD (F4_PER_CHUNK / 256)       // 4 (front-batched, MLP_p1=4)
#define SHIFT_ELEMS 8
#define SGRID (B_ * (PIX_PER_IMG / (256 * SHIFT_ELEMS)))  // 4096 shift blocks
#define FP_SCALE 1048576.0f                      // 2^20 (exact float scaling)

// Scratch (no allocations allowed) — zero-init; self-reset by shift kernel.
__device__ long long    g_tot[B_ * 3];   // fixed-point (m00,m10,m01) per batch
__device__ unsigned int g_done;          // shift completion counter

// ---------------------------------------------------------------------------
// Stage 1: mk moments. Block partials reduced deterministically (butterfly +
// fixed-order smem sum), then committed as 2^20 fixed-point via integer
// atomicAdd — associative, so the total is deterministic regardless of
// arrival order. No inter-block protocol, no finalize stage, no tail.
// ---------------------------------------------------------------------------
__global__ __launch_bounds__(256) void moments_kernel(const float* __restrict__ mk)
{
    const int b     = blockIdx.y;
    const int chunk = blockIdx.x;       // 0..63
    const int t     = threadIdx.x;      // 0..255
    const int lane  = t & 31;
    const int wid   = t >> 5;           // 0..7

    const float4* base =
        (const float4*)(mk + (size_t)b * PIX_PER_IMG) + chunk * F4_PER_CHUNK;

    // Front-batch all 4 independent loads (MLP_p1=4).
    float4 v[F4_PER_THREAD];
#pragma unroll
    for (int i = 0; i < F4_PER_THREAD; i++)
        v[i] = base[t + i * 256];

    float s0 = 0.f, s1 = 0.f, s2 = 0.f;
#pragma unroll
    for (int i = 0; i < F4_PER_THREAD; i++) {
        const int p = chunk * (F4_PER_CHUNK * 4) + (t + i * 256) * 4;
        const int h = p >> 9;
        const int w = p & (W_ - 1);
        const float ry  = (float)(h - (H_ / 2));
        const float rx0 = (float)(w - (W_ / 2));
        const float sum = v[i].x + v[i].y + v[i].z + v[i].w;
        s0 += sum;
        s2 += ry * sum;
        s1 += rx0 * v[i].x + (rx0 + 1.f) * v[i].y + (rx0 + 2.f) * v[i].z
            + (rx0 + 3.f) * v[i].w;
    }

    // Warp butterfly reduce (deterministic fixed order)
#pragma unroll
    for (int m = 16; m > 0; m >>= 1) {
        s0 += __shfl_xor_sync(0xffffffffu, s0, m);
        s1 += __shfl_xor_sync(0xffffffffu, s1, m);
        s2 += __shfl_xor_sync(0xffffffffu, s2, m);
    }

    __shared__ float w0[8], w1[8], w2[8];
    if (lane == 0) { w0[wid] = s0; w1[wid] = s1; w2[wid] = s2; }
    __syncthreads();

    if (t == 0) {
        float r0 = 0.f, r1 = 0.f, r2 = 0.f;
#pragma unroll
        for (int i = 0; i < 8; i++) { r0 += w0[i]; r1 += w1[i]; r2 += w2[i]; }
        // Exact *2^20 scaling; llrintf error <= 0.5 fixed units per block.
        atomicAdd((unsigned long long*)&g_tot[b * 3 + 0],
                  (unsigned long long)llrintf(r0 * FP_SCALE));
        atomicAdd((unsigned long long*)&g_tot[b * 3 + 1],
                  (unsigned long long)llrintf(r1 * FP_SCALE));
        atomicAdd((unsigned long long*)&g_tot[b * 3 + 2],
                  (unsigned long long)llrintf(r2 * FP_SCALE));
    }
}

// ---------------------------------------------------------------------------
// Stage 2: shifted copy. Thread 0 of each block derives (dx,dy) from the
// fixed-point totals (2 double divides per BLOCK, not per thread) and
// broadcasts via shared memory. Kernel boundary guarantees atomics are
// visible. rint = round-half-even, matching jnp.round.
// Last block resets totals for the next graph replay.
// ---------------------------------------------------------------------------
__global__ __launch_bounds__(256) void shift_kernel(const float4* __restrict__ x,
                                                    float4* __restrict__ out)
{
    const int b    = blockIdx.y;
    const int base = blockIdx.x * (256 * SHIFT_ELEMS);   // pixel base in image
    const int t    = threadIdx.x;

    __shared__ int s_dx, s_dy;
    if (t == 0) {
        const long long t0 = g_tot[b * 3 + 0];
        const long long t1 = g_tot[b * 3 + 1];
        const long long t2 = g_tot[b * 3 + 2];
        const double den = fmax(1048.576, (double)t0);   // 0.001 * 2^20 floor
        s_dx = (int)rint((double)t1 / den);
        s_dy = (int)rint((double)t2 / den);
    }
    __syncthreads();
    const int dx = s_dx;
    const int dy = s_dy;

    const float4* xb = x + ((size_t)b << 18);
    float4* ob       = out + ((size_t)b << 18);

    float4 v[SHIFT_ELEMS];
#pragma unroll
    for (int k = 0; k < SHIFT_ELEMS; k++) {
        const int p = base + k * 256 + t;
        const int h = p >> 9;
        const int w = p & (W_ - 1);
        const int sh = h + dy;
        const int sw = w + dx;
        v[k] = make_float4(0.f, 0.f, 0.f, 0.f);
        if ((unsigned)sh < (unsigned)H_ && (unsigned)sw < (unsigned)W_)
            v[k] = xb[(sh << 9) + sw];
    }
#pragma unroll
    for (int k = 0; k < SHIFT_ELEMS; k++)
        ob[base + k * 256 + t] = v[k];

    // Replay cleanup: every block has read g_tot before incrementing g_done
    // (program order via the broadcast syncthreads), so last block may reset.
    __syncthreads();
    if (t == 0) {
        if (atomicAdd(&g_done, 1u) == SGRID - 1) {
#pragma unroll
            for (int i = 0; i < B_ * 3; i++) g_tot[i] = 0ll;
            g_done = 0u;
            __threadfence();
        }
    }
}

// ---------------------------------------------------------------------------
extern "C" void kernel_launch(void* const* d_in, const int* in_sizes, int n_in,
                              void* d_out, int out_size)
{
    const float* x  = (const float*)d_in[0];   // [32,512,512,4]
    const float* mk = (const float*)d_in[1];   // [32,512,512,1]

    dim3 g1(CHUNKS, B_);                       // (64, 32) = 2048 blocks
    moments_kernel<<<g1, 256>>>(mk);

    dim3 g2(PIX_PER_IMG / (256 * SHIFT_ELEMS), B_);   // (128, 32)
    shift_kernel<<<g2, 256>>>((const float4*)x, (float4*)d_out);
}